// round 5
// baseline (speedup 1.0000x reference)
#include <cuda_runtime.h>
#include <cuda_fp16.h>
#include <cstdint>

// y[m,n] = mask[m] ? x[m,:]·W_v[n,:] : x[m,:]·W_t[n,:]
// Mask-partitioned single GEMM, fp16 m16n8k16 mma.sync, fp32 accumulate.
// x/W pre-converted to fp16 in MMA fragment order (1 LDS.128 per A-frag,
// 1 LDS.64 per B-frag, linear cp.async). This round: 2-kt stages (16 barriers
// instead of 32), 3-stage cp.async pipeline, explicit register frag
// double-buffering.

#define M_TOTAL 32768
#define K_DIM   1024
#define N_DIM   1024
#define BM 128
#define BN 128
#define BK 32
#define NK (K_DIM / BK)              // 32 k-panels
#define NPAIR (NK / 2)               // 16 stage-iterations
#define THREADS 128
#define M_PAD 32896                  // 257 tiles * 128
#define NMT (M_PAD / BM)             // 257

#define PANEL_H  4096                // halves per 8KB panel (128 rows x 32 k)
#define APANEL_B 8192
#define STAGE_B  32768               // 2 A panels + 2 B panels
#define STAGES 3
#define DYN_SMEM (STAGES * STAGE_B)  // 96 KB

// ------------------------------------------------------------- device state
__device__ __half g_x[(size_t)M_PAD * K_DIM];    // [mtile][kpanel][frag order]
__device__ __half g_wv[(size_t)N_DIM * K_DIM];   // [ntile][kpanel][frag order]
__device__ __half g_wt[(size_t)N_DIM * K_DIM];
__device__ int   g_perm[M_PAD];                  // slot -> source row (-1 dead)
__device__ int   g_nv, g_cv, g_ct;
__device__ int   g_mask_is_u8;

// ------------------------------------------------------------- helpers
__device__ __forceinline__ bool mask_at(const unsigned char* m, int i) {
    return g_mask_is_u8 ? (m[i] != 0) : (((const int*)m)[i] != 0);
}

__device__ __forceinline__ uint32_t smem_u32(const void* p) {
    uint32_t a;
    asm("{ .reg .u64 t; cvta.to.shared.u64 t, %1; cvt.u32.u64 %0, t; }"
        : "=r"(a) : "l"(p));
    return a;
}

__device__ __forceinline__ void cp16(uint32_t saddr, const void* g) {
    asm volatile("cp.async.cg.shared.global [%0], [%1], 16;"
                 :: "r"(saddr), "l"(g) : "memory");
}

__device__ __forceinline__ void mma_f16(float* d, const uint32_t* a, const uint32_t* b) {
    asm volatile(
        "mma.sync.aligned.m16n8k16.row.col.f32.f16.f16.f32 "
        "{%0,%1,%2,%3}, {%4,%5,%6,%7}, {%8,%9}, {%0,%1,%2,%3};"
        : "+f"(d[0]), "+f"(d[1]), "+f"(d[2]), "+f"(d[3])
        : "r"(a[0]), "r"(a[1]), "r"(a[2]), "r"(a[3]), "r"(b[0]), "r"(b[1]));
}

// ------------------------------------------------------------- prep kernels
// K0: block 0 detects mask dtype + inits counters; all blocks clear perm.
__global__ void k0_init(const unsigned char* __restrict__ m) {
    int tid = threadIdx.x;
    int gi = blockIdx.x * 1024 + tid;
    if (gi < M_PAD) g_perm[gi] = -1;
    if (blockIdx.x == 0) {
        __shared__ int found;
        if (tid == 0) { found = 0; g_nv = 0; g_cv = 0; g_ct = 0; }
        __syncthreads();
        int local = 0;
        for (int i = tid; i < 8192; i += 1024)
            if (m[4 * i + 1] | m[4 * i + 2] | m[4 * i + 3]) local = 1;
        if (local) atomicOr(&found, 1);
        __syncthreads();
        if (tid == 0) g_mask_is_u8 = found;
    }
}

__global__ void k1_count(const unsigned char* __restrict__ m) {
    int row = blockIdx.x * 256 + threadIdx.x;
    bool mv = mask_at(m, row);
    unsigned bal = __ballot_sync(0xffffffffu, mv);
    if ((threadIdx.x & 31) == 0) atomicAdd(&g_nv, __popc(bal));
}

__global__ void k2_assign(const unsigned char* __restrict__ m) {
    __shared__ int s_v[8], s_t[8];
    __shared__ int s_baseV, s_baseT;
    int tid = threadIdx.x;
    int row = blockIdx.x * 256 + tid;
    int warp = tid >> 5, lane = tid & 31;
    bool mv = mask_at(m, row);
    unsigned bal = __ballot_sync(0xffffffffu, mv);
    int lpv = __popc(bal & ((1u << lane) - 1));
    int lpt = lane - lpv;
    if (lane == 0) { s_v[warp] = __popc(bal); s_t[warp] = 32 - __popc(bal); }
    __syncthreads();
    if (tid == 0) {
        int av = 0, at = 0;
        #pragma unroll
        for (int w = 0; w < 8; w++) {
            int tv = s_v[w]; s_v[w] = av; av += tv;
            int tt = s_t[w]; s_t[w] = at; at += tt;
        }
        s_baseV = atomicAdd(&g_cv, av);
        s_baseT = atomicAdd(&g_ct, at);
    }
    __syncthreads();
    int pad = (g_nv + 127) & ~127;
    int slot = mv ? (s_baseV + s_v[warp] + lpv)
                  : (pad + s_baseT + s_t[warp] + lpt);
    g_perm[slot] = row;
}

// K3: gather rows via perm, convert to fp16, write A panels in fragment order.
__global__ void k3_xconv(const float* __restrict__ x) {
    __shared__ int sperm[BM];
    const int mt = blockIdx.x, kp = blockIdx.y;
    const int tid = threadIdx.x;
    if (tid < BM) sperm[tid] = g_perm[mt * BM + tid];
    __syncthreads();

    __half* dst = g_x + ((size_t)mt * NK + kp) * PANEL_H;
    const int kbase = kp * BK;

    #pragma unroll
    for (int q = 0; q < 2; q++) {
        int h0 = tid * 8 + q * 2048;
        int b = h0 >> 8;                 // 16x16 block
        int rb = b >> 1, ks = b & 1;
        int lane = (h0 >> 3) & 31;
        int grp = lane >> 2, qid = lane & 3;
        __half vals[8];
        #pragma unroll
        for (int reg = 0; reg < 4; reg++) {
            int row = rb * 16 + grp + 8 * (reg & 1);
            int k   = ks * 16 + 2 * qid + 8 * (reg >> 1);
            int src = sperm[row];
            float2 f = (src >= 0)
                ? *(const float2*)(x + (size_t)src * K_DIM + kbase + k)
                : make_float2(0.f, 0.f);
            vals[reg * 2 + 0] = __float2half_rn(f.x);
            vals[reg * 2 + 1] = __float2half_rn(f.y);
        }
        *(uint4*)(dst + h0) = *(const uint4*)vals;
    }
}

// K4: weights -> fp16 B panels in fragment order.
__global__ void k4_wconv(const float* __restrict__ Wv, const float* __restrict__ Wt) {
    const int nt = blockIdx.x, kp = blockIdx.y;
    const float* src = blockIdx.z ? Wt : Wv;
    __half* dst = (blockIdx.z ? g_wt : g_wv) + ((size_t)nt * NK + kp) * PANEL_H;
    const int tid = threadIdx.x;
    const int kbase = kp * BK;

    #pragma unroll
    for (int q = 0; q < 2; q++) {
        int h0 = tid * 8 + q * 2048;
        __half vals[8];
        #pragma unroll
        for (int j = 0; j < 8; j++) {
            int h = h0 + j;
            int b = h >> 7;
            int nb = b >> 1, ks = b & 1;
            int lane = (h >> 2) & 31;
            int v = h & 3;
            int grp = lane >> 2, qid = lane & 3;
            int n = nt * 128 + nb * 8 + grp;
            int k = kbase + ks * 16 + 2 * qid + 8 * (v >> 1) + (v & 1);
            vals[j] = __float2half_rn(src[(size_t)n * K_DIM + k]);
        }
        *(uint4*)(dst + h0) = *(const uint4*)vals;
    }
}

// ------------------------------------------------------------- GEMM
extern __shared__ char dsmem[];

__global__ __launch_bounds__(THREADS, 2)
void gemm_kernel(float* __restrict__ out)
{
    const int tid  = threadIdx.x;
    const int warp = tid >> 5;
    const int lane = tid & 31;
    const int grp  = lane >> 2;
    const int qid  = lane & 3;
    const int rb0  = (warp >> 1) * 4;        // A block base (64 rows)
    const int nb0  = (warp & 1) * 8;         // B block base (64 cols)
    const int blockN = blockIdx.x * BN;
    const int mt     = blockIdx.y;

    const int pad = (g_nv + 127) & ~127;
    const char* gA = (const char*)(g_x + (size_t)mt * NK * PANEL_H);
    const char* gB = (const char*)(((mt * BM < pad) ? g_wv : g_wt)
                                   + (size_t)blockIdx.x * NK * PANEL_H);

    const uint32_t sbase = smem_u32(dsmem);

    float acc[4][8][4];
    #pragma unroll
    for (int i = 0; i < 4; i++)
        #pragma unroll
        for (int j = 0; j < 8; j++)
            #pragma unroll
            for (int c = 0; c < 4; c++) acc[i][j][c] = 0.f;

    // load stage s (k-panels 2s, 2s+1): [A0][A1][B0][B1], one commit group
    auto ISSUE = [&](int s) {
        const uint32_t sst = sbase + (s % STAGES) * STAGE_B;
        const char* srcA = gA + (size_t)s * 2 * APANEL_B;
        const char* srcB = gB + (size_t)s * 2 * APANEL_B;
        #pragma unroll
        for (int i = 0; i < 8; i++) {
            uint32_t off = (uint32_t)(i * 2048 + tid * 16);
            cp16(sst + off, srcA + off);
        }
        #pragma unroll
        for (int i = 0; i < 8; i++) {
            uint32_t off = (uint32_t)(i * 2048 + tid * 16);
            cp16(sst + 2 * APANEL_B + off, srcB + off);
        }
        asm volatile("cp.async.commit_group;" ::: "memory");
    };

    auto LDFRAG = [&](const char* stage, int c, uint32_t a[4][4], uint32_t b[8][2]) {
        const int sub = c >> 1, ks = c & 1;          // panel, k16-half
        const char* sA = stage + sub * APANEL_B;
        const char* sB = stage + 2 * APANEL_B + sub * APANEL_B;
        #pragma unroll
        for (int i = 0; i < 4; i++) {
            uint4 v = *(const uint4*)(sA + ((rb0 + i) * 2 + ks) * 512 + lane * 16);
            a[i][0] = v.x; a[i][1] = v.y; a[i][2] = v.z; a[i][3] = v.w;
        }
        #pragma unroll
        for (int j = 0; j < 8; j++) {
            uint2 v = *(const uint2*)(sB + ((nb0 + j) * 2 + ks) * 256 + lane * 8);
            b[j][0] = v.x; b[j][1] = v.y;
        }
    };

    ISSUE(0); ISSUE(1);

    uint32_t a[2][4][4], b[2][8][2];

    for (int it = 0; it < NPAIR; it++) {
        asm volatile("cp.async.wait_group 1;" ::: "memory");   // stage it ready
        __syncthreads();
        if (it + 2 < NPAIR) ISSUE(it + 2);                     // into freed stage
        const char* stage = dsmem + (it % STAGES) * STAGE_B;

        LDFRAG(stage, 0, a[0], b[0]);
        #pragma unroll
        for (int c = 0; c < 4; c++) {
            if (c < 3) LDFRAG(stage, c + 1, a[(c + 1) & 1], b[(c + 1) & 1]);
            #pragma unroll
            for (int i = 0; i < 4; i++)
                #pragma unroll
                for (int j = 0; j < 8; j++)
                    mma_f16(acc[i][j], a[c & 1][i], b[c & 1][j]);
        }
    }

    // epilogue: scatter rows through perm
    const int blockM = mt * BM;
    #pragma unroll
    for (int i = 0; i < 4; i++) {
        int r = rb0 * 16 + i * 16 + grp;
        int d0 = g_perm[blockM + r];
        int d1 = g_perm[blockM + r + 8];
        #pragma unroll
        for (int j = 0; j < 8; j++) {
            int col = blockN + nb0 * 8 + j * 8 + qid * 2;
            if (d0 >= 0)
                *(float2*)(out + (size_t)d0 * N_DIM + col) =
                    make_float2(acc[i][j][0], acc[i][j][1]);
            if (d1 >= 0)
                *(float2*)(out + (size_t)d1 * N_DIM + col) =
                    make_float2(acc[i][j][2], acc[i][j][3]);
        }
    }
}

// ------------------------------------------------------------- launch
extern "C" void kernel_launch(void* const* d_in, const int* in_sizes, int n_in,
                              void* d_out, int out_size)
{
    const float*         x    = (const float*)d_in[0];
    const unsigned char* mask = (const unsigned char*)d_in[1];
    const float*         Wv   = (const float*)d_in[2];
    const float*         Wt   = (const float*)d_in[3];
    float*               out  = (float*)d_out;

    static bool attr_set = false;
    if (!attr_set) {
        cudaFuncSetAttribute(gemm_kernel,
                             cudaFuncAttributeMaxDynamicSharedMemorySize, DYN_SMEM);
        attr_set = true;
    }

    k0_init<<<(M_PAD + 1023) / 1024, 1024>>>(mask);
    k1_count<<<M_TOTAL / 256, 256>>>(mask);
    k2_assign<<<M_TOTAL / 256, 256>>>(mask);
    k3_xconv<<<dim3(NMT, NK), 256>>>(x);
    k4_wconv<<<dim3(N_DIM / 128, NK, 2), 256>>>(Wv, Wt);
    gemm_kernel<<<dim3(N_DIM / BN, NMT), THREADS, DYN_SMEM>>>(out);
}